// round 17
// baseline (speedup 1.0000x reference)
#include <cuda_runtime.h>
#include <cuda_bf16.h>
#include <cstdint>

#define ND 128
#define HID 16
#define N_MAX 100000

typedef unsigned long long u64;

// Device-global scratch; statically zeroed; each run restores its own state.
__device__ __align__(16) int g_udi[N_MAX];   // cnt*2^24 + sum(s*2^16); reset by node_kernel
__device__ __align__(16) int g_si[N_MAX];    // per-node fixed-point: 2^24 + round(s*2^16)
__device__ float    g_acc;                   // reset by last node_kernel block
__device__ unsigned g_done;                  // wraps via atomicInc

__device__ __forceinline__ float ftanh(float v) {
    return 1.0f - __fdividef(2.0f, __expf(2.0f * v) + 1.0f);
}
__device__ __forceinline__ uint32_t packbf(float lo, float hi) {
    __nv_bfloat162 p = __floats2bfloat162_rn(lo, hi);
    return *(uint32_t*)&p;
}

#define LDSM4(r, addr) \
    asm volatile("ldmatrix.sync.aligned.m8n8.x4.shared.b16 {%0,%1,%2,%3}, [%4];" \
        : "=r"((r)[0]), "=r"((r)[1]), "=r"((r)[2]), "=r"((r)[3]) : "r"(addr))
#define LDSM2(r, addr) \
    asm volatile("ldmatrix.sync.aligned.m8n8.x2.shared.b16 {%0,%1}, [%2];" \
        : "=r"((r)[0]), "=r"((r)[1]) : "r"(addr))
#define MMA16816(c, a, b) \
    asm volatile("mma.sync.aligned.m16n8k16.row.col.f32.bf16.bf16.f32 " \
        "{%0,%1,%2,%3}, {%4,%5,%6,%7}, {%8,%9}, {%0,%1,%2,%3};" \
        : "+f"((c)[0]), "+f"((c)[1]), "+f"((c)[2]), "+f"((c)[3]) \
        : "r"((a)[0]), "r"((a)[1]), "r"((a)[2]), "r"((a)[3]), "r"((b)[0]), "r"((b)[1]))

// ---------------- K1: fully fragment-resident 3-layer MLP ------------------
#define T_TPB 128
#define XSTRIDE 272      // bytes per x row (128 bf16 = 256B + 16B pad)

__global__ void __launch_bounds__(T_TPB) mlp_kernel(
    const float* __restrict__ x,
    const float* __restrict__ W1, const float* __restrict__ b1,
    const float* __restrict__ W2, const float* __restrict__ b2,
    const float* __restrict__ W3, const float* __restrict__ b3,
    const float* __restrict__ Wc,
    int n)
{
    __shared__ __align__(16) char sPool[T_TPB * XSTRIDE];   // x tile bf16
    __shared__ __align__(16) char sBT[16 * XSTRIDE];        // W1^T bf16 [16 n][128 k]
    __shared__ float sW2f[HID * HID], sW3f[HID * HID];
    __shared__ float sb1[HID], sb2[HID], sb3[HID], sWc[HID];

    int tid = threadIdx.x;
    int w = tid >> 5;
    int lane = tid & 31;
    int tileBase = blockIdx.x * T_TPB;

    uint32_t sXb = (uint32_t)__cvta_generic_to_shared(sPool);
    uint32_t sBTb = (uint32_t)__cvta_generic_to_shared(sBT);

    // ---- stage x: coalesced rows -> bf16 smem tile (one row per warp-LDG) --
#pragma unroll 8
    for (int i = 0; i < 32; i++) {
        int row = i * 4 + w;
        int gn = min(tileBase + row, n - 1);
        float4 vv = ((const float4*)(x + (size_t)gn * ND))[lane];
        uint2 pk = make_uint2(packbf(vv.x, vv.y), packbf(vv.z, vv.w));
        *(uint2*)(sPool + row * XSTRIDE + lane * 8) = pk;
    }

    // ---- W1^T bf16: thread tid = k row of W1; scatter 16 bf16 into column k
    {
        const float4* wrow = (const float4*)(W1 + tid * HID);
        float4 wv[4] = {wrow[0], wrow[1], wrow[2], wrow[3]};
        const float* wf = (const float*)wv;
#pragma unroll
        for (int nn = 0; nn < HID; nn++)
            *(__nv_bfloat16*)(sBT + nn * XSTRIDE + tid * 2) = __float2bfloat16(wf[nn]);
    }
    if (tid < HID * HID / 2) {   // 128 threads load 256 floats of W2/W3
        ((float2*)sW2f)[tid] = ((const float2*)W2)[tid];
        ((float2*)sW3f)[tid] = ((const float2*)W3)[tid];
    }
    if (tid < HID) {
        sb1[tid] = b1[tid]; sb2[tid] = b2[tid]; sb3[tid] = b3[tid]; sWc[tid] = Wc[tid];
    }
    __syncthreads();

    // ---- layer 1 MMAs ----
    int rA = (lane & 7) + ((lane >> 3) & 1) * 8;
    uint32_t aOff = (uint32_t)((lane >> 4) & 1) * 16u;
    uint32_t aB0 = sXb + (uint32_t)(32 * w + rA) * XSTRIDE + aOff;
    uint32_t aB1 = aB0 + 16u * XSTRIDE;
    uint32_t bB0 = sBTb + (uint32_t)(lane & 7) * XSTRIDE + (uint32_t)((lane >> 3) & 1) * 16u;
    uint32_t bB1 = bB0 + 8u * XSTRIDE;

    float c00[4] = {0, 0, 0, 0}, c01[4] = {0, 0, 0, 0};
    float c10[4] = {0, 0, 0, 0}, c11[4] = {0, 0, 0, 0};

#pragma unroll
    for (int k = 0; k < 8; k++) {
        uint32_t a0[4], a1[4], b0[2], b1v[2];
        uint32_t kb = (uint32_t)k * 32u;
        LDSM4(a0, aB0 + kb);
        LDSM4(a1, aB1 + kb);
        LDSM2(b0, bB0 + kb);
        LDSM2(b1v, bB1 + kb);
        MMA16816(c00, a0, b0);
        MMA16816(c01, a0, b1v);
        MMA16816(c10, a1, b0);
        MMA16816(c11, a1, b1v);
    }

    int g = lane >> 2, tig = lane & 3;
    int k0 = 2 * tig, k1 = 2 * tig + 1, k8 = 8 + 2 * tig, k9 = 9 + 2 * tig;

    // ---- bias + tanh in fragments -> layer-2 A fragments (bf16) ----
    float bl0 = sb1[k0], bl1 = sb1[k1], bl8 = sb1[k8], bl9 = sb1[k9];
    uint32_t A0[4], A1[4];
    A0[0] = packbf(ftanh(c00[0] + bl0), ftanh(c00[1] + bl1));
    A0[1] = packbf(ftanh(c00[2] + bl0), ftanh(c00[3] + bl1));
    A0[2] = packbf(ftanh(c01[0] + bl8), ftanh(c01[1] + bl9));
    A0[3] = packbf(ftanh(c01[2] + bl8), ftanh(c01[3] + bl9));
    A1[0] = packbf(ftanh(c10[0] + bl0), ftanh(c10[1] + bl1));
    A1[1] = packbf(ftanh(c10[2] + bl0), ftanh(c10[3] + bl1));
    A1[2] = packbf(ftanh(c11[0] + bl8), ftanh(c11[1] + bl9));
    A1[3] = packbf(ftanh(c11[2] + bl8), ftanh(c11[3] + bl9));

    // ---- layer 2: B frags from sW2f; 4 MMAs ----
    uint32_t B0[2], B1[2];
    B0[0] = packbf(sW2f[k0 * HID + g], sW2f[k1 * HID + g]);
    B0[1] = packbf(sW2f[k8 * HID + g], sW2f[k9 * HID + g]);
    B1[0] = packbf(sW2f[k0 * HID + g + 8], sW2f[k1 * HID + g + 8]);
    B1[1] = packbf(sW2f[k8 * HID + g + 8], sW2f[k9 * HID + g + 8]);

    float d00[4] = {0, 0, 0, 0}, d01[4] = {0, 0, 0, 0};
    float d10[4] = {0, 0, 0, 0}, d11[4] = {0, 0, 0, 0};
    MMA16816(d00, A0, B0);
    MMA16816(d01, A0, B1);
    MMA16816(d10, A1, B0);
    MMA16816(d11, A1, B1);

    // ---- bias + tanh -> layer-3 A fragments ----
    bl0 = sb2[k0]; bl1 = sb2[k1]; bl8 = sb2[k8]; bl9 = sb2[k9];
    A0[0] = packbf(ftanh(d00[0] + bl0), ftanh(d00[1] + bl1));
    A0[1] = packbf(ftanh(d00[2] + bl0), ftanh(d00[3] + bl1));
    A0[2] = packbf(ftanh(d01[0] + bl8), ftanh(d01[1] + bl9));
    A0[3] = packbf(ftanh(d01[2] + bl8), ftanh(d01[3] + bl9));
    A1[0] = packbf(ftanh(d10[0] + bl0), ftanh(d10[1] + bl1));
    A1[1] = packbf(ftanh(d10[2] + bl0), ftanh(d10[3] + bl1));
    A1[2] = packbf(ftanh(d11[0] + bl8), ftanh(d11[1] + bl9));
    A1[3] = packbf(ftanh(d11[2] + bl8), ftanh(d11[3] + bl9));

    // ---- layer 3 ----
    B0[0] = packbf(sW3f[k0 * HID + g], sW3f[k1 * HID + g]);
    B0[1] = packbf(sW3f[k8 * HID + g], sW3f[k9 * HID + g]);
    B1[0] = packbf(sW3f[k0 * HID + g + 8], sW3f[k1 * HID + g + 8]);
    B1[1] = packbf(sW3f[k8 * HID + g + 8], sW3f[k9 * HID + g + 8]);

#pragma unroll
    for (int q = 0; q < 4; q++) { d00[q] = 0; d01[q] = 0; d10[q] = 0; d11[q] = 0; }
    MMA16816(d00, A0, B0);
    MMA16816(d01, A0, B1);
    MMA16816(d10, A1, B0);
    MMA16816(d11, A1, B1);

    // ---- final: tanh + Wc contraction; quad shuffle-reduce over tig ----
    bl0 = sb3[k0]; bl1 = sb3[k1]; bl8 = sb3[k8]; bl9 = sb3[k9];
    float wc0 = sWc[k0], wc1 = sWc[k1], wc8 = sWc[k8], wc9 = sWc[k9];

    float p0 = ftanh(d00[0] + bl0) * wc0 + ftanh(d00[1] + bl1) * wc1
             + ftanh(d01[0] + bl8) * wc8 + ftanh(d01[1] + bl9) * wc9;   // row g
    float p1 = ftanh(d00[2] + bl0) * wc0 + ftanh(d00[3] + bl1) * wc1
             + ftanh(d01[2] + bl8) * wc8 + ftanh(d01[3] + bl9) * wc9;   // row g+8
    float p2 = ftanh(d10[0] + bl0) * wc0 + ftanh(d10[1] + bl1) * wc1
             + ftanh(d11[0] + bl8) * wc8 + ftanh(d11[1] + bl9) * wc9;   // row g+16
    float p3 = ftanh(d10[2] + bl0) * wc0 + ftanh(d10[3] + bl1) * wc1
             + ftanh(d11[2] + bl8) * wc8 + ftanh(d11[3] + bl9) * wc9;   // row g+24

    unsigned fm = 0xffffffffu;
    p0 += __shfl_xor_sync(fm, p0, 1); p0 += __shfl_xor_sync(fm, p0, 2);
    p1 += __shfl_xor_sync(fm, p1, 1); p1 += __shfl_xor_sync(fm, p1, 2);
    p2 += __shfl_xor_sync(fm, p2, 1); p2 += __shfl_xor_sync(fm, p2, 2);
    p3 += __shfl_xor_sync(fm, p3, 1); p3 += __shfl_xor_sync(fm, p3, 2);

    if (tig == 0) {
        int rbase = tileBase + 32 * w + g;
        // clamped duplicate writes carry identical values -> benign
        g_si[min(rbase,      n - 1)] = (1 << 24) + __float2int_rn(p0 * 65536.0f);
        g_si[min(rbase + 8,  n - 1)] = (1 << 24) + __float2int_rn(p1 * 65536.0f);
        g_si[min(rbase + 16, n - 1)] = (1 << 24) + __float2int_rn(p2 * 65536.0f);
        g_si[min(rbase + 24, n - 1)] = (1 << 24) + __float2int_rn(p3 * 65536.0f);
    }
}

// ------ K2: single edge pass: udi[src] += si[dst]  (one RED.ADD.32) -------
#define E_TPB 256
#define E_EPT 8

__global__ void __launch_bounds__(E_TPB) edge_kernel(
    const int* __restrict__ src, const int* __restrict__ dst, int e)
{
    long base = (long)(blockIdx.x * E_TPB + threadIdx.x) * E_EPT;
    if (base + E_EPT <= e) {
        int4 da = *(const int4*)(dst + base);
        int4 db = *(const int4*)(dst + base + 4);
        int4 sa = *(const int4*)(src + base);
        int4 sb = *(const int4*)(src + base + 4);
        int v0 = __ldg(&g_si[da.x]), v1 = __ldg(&g_si[da.y]);
        int v2 = __ldg(&g_si[da.z]), v3 = __ldg(&g_si[da.w]);
        int v4 = __ldg(&g_si[db.x]), v5 = __ldg(&g_si[db.y]);
        int v6 = __ldg(&g_si[db.z]), v7 = __ldg(&g_si[db.w]);
        atomicAdd(&g_udi[sa.x], v0);
        atomicAdd(&g_udi[sa.y], v1);
        atomicAdd(&g_udi[sa.z], v2);
        atomicAdd(&g_udi[sa.w], v3);
        atomicAdd(&g_udi[sb.x], v4);
        atomicAdd(&g_udi[sb.y], v5);
        atomicAdd(&g_udi[sb.z], v6);
        atomicAdd(&g_udi[sb.w], v7);
    } else {
        for (long i = base; i < e; i++)
            atomicAdd(&g_udi[src[i]], __ldg(&g_si[dst[i]]));
    }
}

// ------ K3: node pass: acc = sum_m u[m]/cnt[m]; sigmoid; reset state ------
#define N_TPB 256

__global__ void __launch_bounds__(N_TPB) node_kernel(
    const float* __restrict__ bc, float* __restrict__ out, int n, float inv_n)
{
    __shared__ float sRed[N_TPB / 32];
    int tid = threadIdx.x;
    int i = blockIdx.x * N_TPB + tid;
    float term = 0.f;

    if (i < n) {
        int v = g_udi[i];
        if (v != 0) {
            int cnt = (v + (1 << 23)) >> 24;
            float u = (float)(v - (cnt << 24)) * (1.0f / 65536.0f);
            term = u * __frcp_rn((float)cnt);
            g_udi[i] = 0;  // restore for next graph replay
        }
    }

    unsigned m = 0xffffffffu;
#pragma unroll
    for (int off = 16; off > 0; off >>= 1)
        term += __shfl_down_sync(m, term, off);
    if ((tid & 31) == 0) sRed[tid >> 5] = term;
    __syncthreads();

    if (tid == 0) {
        float v = 0.f;
#pragma unroll
        for (int wq = 0; wq < N_TPB / 32; wq++) v += sRed[wq];
        atomicAdd(&g_acc, v);
        __threadfence();
        unsigned ticket = atomicInc(&g_done, gridDim.x - 1);  // wraps to 0 on last
        if (ticket == gridDim.x - 1) {
            float z = g_acc * inv_n + bc[0];
            out[0] = 1.0f / (1.0f + __expf(-z));
            g_acc = 0.f;  // restore for next replay
        }
    }
}

extern "C" void kernel_launch(void* const* d_in, const int* in_sizes, int n_in,
                              void* d_out, int out_size) {
    const float* x    = (const float*)d_in[0];
    const int*   esrc = (const int*)  d_in[1];
    const int*   edst = (const int*)  d_in[2];
    const float* W1   = (const float*)d_in[3];
    const float* b1   = (const float*)d_in[4];
    const float* W2   = (const float*)d_in[5];
    const float* b2   = (const float*)d_in[6];
    const float* W3   = (const float*)d_in[7];
    const float* b3   = (const float*)d_in[8];
    const float* Wc   = (const float*)d_in[9];
    const float* bc   = (const float*)d_in[10];
    float* out = (float*)d_out;

    int n = in_sizes[0] / ND;
    int e = in_sizes[1];
    if (n > N_MAX) n = N_MAX;

    int nMlp = (n + T_TPB - 1) / T_TPB;
    mlp_kernel<<<nMlp, T_TPB>>>(x, W1, b1, W2, b2, W3, b3, Wc, n);

    int nEdge = (e + E_TPB * E_EPT - 1) / (E_TPB * E_EPT);
    edge_kernel<<<nEdge, E_TPB>>>(esrc, edst, e);

    int nNode = (n + N_TPB - 1) / N_TPB;
    node_kernel<<<nNode, N_TPB>>>(bc, out, n, 1.0f / (float)n);
}